// round 4
// baseline (speedup 1.0000x reference)
#include <cuda_runtime.h>
#include <math.h>
#include <stdint.h>

// ---------------- problem constants ----------------
#define D_FULL   256
#define NHEAD    4
#define HDIM     64
#define NP       16
#define NM       32
#define NR       2
#define NB       1024
#define NL       128
#define NK       8
#define NNEG     2048
#define NPOS     (NB * NK)        /* 8192 */
#define NW       (NPOS + NNEG)    /* 10240 */
#define NUM_LABELS 131072
#define FP       (NHEAD * NP)     /* 64 poly feats per row */
#define FR       (NHEAD * NR * NM)/* 256 prf feats per row */
#define TQ       8                /* queries per score block */

// ---------------- device scratch ----------------
__device__ float g_anchT[HDIM * NP];   // normalized anchors, transposed [d][p]
__device__ float g_Pq[NB * FP];        // query poly feats, row-major
__device__ float g_Rq[NB * FR];        // query prf feats, row-major
__device__ float g_PwT[FP * NW];       // W poly feats, TRANSPOSED [feat][row]
__device__ float g_RwT[FR * NW];       // W prf feats, TRANSPOSED [feat][row]
__device__ float g_pos[NPOS];
__device__ float g_Z[NB];

// ---------------- anchors ----------------
__global__ void __launch_bounds__(256) anch_kernel(const float* __restrict__ anchors)
{
    __shared__ float inv[NP];
    int t = threadIdx.x;
    if (t < NP) {
        float s = 0.f;
        #pragma unroll 8
        for (int d = 0; d < HDIM; d++) {
            float v = anchors[t * HDIM + d];
            s = fmaf(v, v, s);
        }
        inv[t] = 1.f / sqrtf(s);
    }
    __syncthreads();
    for (int i = t; i < HDIM * NP; i += blockDim.x) {
        int p = i & (NP - 1);
        int d = i >> 4;
        g_anchT[i] = anchors[p * HDIM + d] * inv[p];
    }
}

// ---------------- shared feature pipeline ----------------
// v = raw component for dim t of the 256-dim row. Global normalize cancels
// under the per-head normalize, so only per-head normalization is done.
// Writes Prow[f*strideP], Rrow[f*strideR].
__device__ __forceinline__ void feat_from_raw(
    float v, int t,
    float* s_x, float* s_ws, const float* s_anch,
    const float* __restrict__ omega,
    float* __restrict__ Prow, int strideP,
    float* __restrict__ Rrow, int strideR,
    float s0, float s1, float t0, float t1, float c0, float c1)
{
    float sq = v * v;
    #pragma unroll
    for (int off = 16; off; off >>= 1) sq += __shfl_xor_sync(0xffffffffu, sq, off);
    if ((t & 31) == 0) s_ws[t >> 5] = sq;
    __syncthreads();
    int h = t >> 6;
    float n = sqrtf(s_ws[2 * h] + s_ws[2 * h + 1]);
    s_x[t] = v / fmaxf(n, 1e-20f);
    __syncthreads();

    // PRF feature: thread t -> (r, hh, m)
    int r  = t >> 7;
    int hh = (t >> 5) & 3;
    int m  = t & 31;
    const float* xh = s_x + hh * HDIM;
    const float* om = omega + ((r * NHEAD + hh) * HDIM) * NM + m;
    float dot = 0.f;
    #pragma unroll 8
    for (int d = 0; d < HDIM; d++) dot = fmaf(xh[d], om[d * NM], dot);
    dot *= 0.125f;                       // omega / sqrt(64)
    float ss = r ? s1 : s0;
    float tt = r ? t1 : t0;
    float cc = r ? c1 : c0;
    float arg = fminf(fmaxf(dot * tt - ss, -20.f), 20.f);
    Rrow[(hh * (NR * NM) + r * NM + m) * strideR] = expf(arg) * cc;

    // poly feature: threads 0..63 -> (h2, p)
    if (t < FP) {
        int h2 = t >> 4, p = t & (NP - 1);
        const float* xh2 = s_x + h2 * HDIM;
        float d2 = 0.f;
        #pragma unroll 8
        for (int d = 0; d < HDIM; d++) d2 = fmaf(xh2[d], s_anch[d * NP + p], d2);
        d2 = fminf(fmaxf(d2, -1.f), 1.f);
        Prow[t * strideP] = d2 * d2 * 0.25f;   // proj^2 / sqrt(16)
    }
}

// ---------------- queries ----------------
__global__ void __launch_bounds__(256) query_feat_kernel(
    const int* __restrict__ indices, const float* __restrict__ mask,
    const float* __restrict__ etab, const float* __restrict__ omega,
    float s0, float s1, float t0, float t1, float c0, float c1)
{
    __shared__ float s_x[D_FULL];
    __shared__ float s_ws[8];
    __shared__ float s_anch[HDIM * NP];
    __shared__ int   s_i[NL];
    __shared__ float s_m[NL];
    int t = threadIdx.x, b = blockIdx.x;

    for (int i = t; i < HDIM * NP; i += blockDim.x) s_anch[i] = g_anchT[i];
    if (t < NL) { s_i[t] = indices[b * NL + t]; s_m[t] = mask[b * NL + t]; }
    __syncthreads();

    float acc = 0.f;
    #pragma unroll 4
    for (int l = 0; l < NL; l++)
        acc = fmaf(s_m[l], etab[(size_t)s_i[l] * D_FULL + t], acc);
    // division by max(sum mask,1) cancels in the per-head normalize

    feat_from_raw(acc, t, s_x, s_ws, s_anch, omega,
                  g_Pq + (size_t)b * FP, 1,
                  g_Rq + (size_t)b * FR, 1,
                  s0, s1, t0, t1, c0, c1);
}

// ---------------- W subset (features stored transposed) ----------------
__global__ void __launch_bounds__(256) w_feat_kernel(
    const int* __restrict__ labels, const int* __restrict__ neg_idx,
    const float* __restrict__ kern, const float* __restrict__ omega,
    float s0, float s1, float t0, float t1, float c0, float c1)
{
    __shared__ float s_x[D_FULL];
    __shared__ float s_ws[8];
    __shared__ float s_anch[HDIM * NP];
    int t = threadIdx.x, row = blockIdx.x;

    for (int i = t; i < HDIM * NP; i += blockDim.x) s_anch[i] = g_anchT[i];

    int col;
    if (row < NPOS) { col = labels[row]; col = col < 0 ? 0 : col; }
    else            { col = neg_idx[row - NPOS]; }
    float v = kern[(size_t)t * NUM_LABELS + col];
    __syncthreads();

    feat_from_raw(v, t, s_x, s_ws, s_anch, omega,
                  g_PwT + row, NW,
                  g_RwT + row, NW,
                  s0, s1, t0, t1, c0, c1);
}

// ---------------- scores + per-query Z ----------------
// warp-uniform sP/sR reads (broadcast LDS); W reads lane-coalesced via
// transposed layout. 8 query accumulators per thread. Unrolls capped to keep
// ptxas's load batching small (no spill, no local memory).
__global__ void __launch_bounds__(512) score_kernel()
{
    __shared__ float sP[TQ * FP];   // 2 KB
    __shared__ float sR[TQ * FR];   // 8 KB
    __shared__ float zacc[TQ];
    int t = threadIdx.x;
    int qbase = blockIdx.x * TQ;

    for (int i = t; i < TQ * FP; i += 512) sP[i] = g_Pq[qbase * FP + i];
    for (int i = t; i < TQ * FR; i += 512) sR[i] = g_Rq[qbase * FR + i];
    if (t < TQ) zacc[t] = 0.f;
    __syncthreads();

    // positives: threads 0..63 -> (ql, k)
    if (t < TQ * NK) {
        int ql = t >> 3;
        int row = (qbase + ql) * NK + (t & 7);
        float tot = 0.f;
        #pragma unroll 1
        for (int h = 0; h < NHEAD; h++) {
            float a = 0.f, b = 0.f;
            #pragma unroll 4
            for (int p = 0; p < NP; p++)
                a = fmaf(sP[ql * FP + h * NP + p], g_PwT[(h * NP + p) * NW + row], a);
            #pragma unroll 4
            for (int i = 0; i < NR * NM; i++)
                b = fmaf(sR[ql * FR + h * NR * NM + i], g_RwT[(h * NR * NM + i) * NW + row], b);
            tot = fmaf(a, b, tot);
        }
        g_pos[row] = tot;
        atomicAdd(&zacc[ql], tot);
    }

    // negatives
    float z0 = 0.f, z1 = 0.f, z2 = 0.f, z3 = 0.f;
    float z4 = 0.f, z5 = 0.f, z6 = 0.f, z7 = 0.f;

    #pragma unroll 1
    for (int j = t; j < NNEG; j += 512) {
        int row = NPOS + j;
        #pragma unroll 1
        for (int h = 0; h < NHEAD; h++) {
            float a0 = 0.f, a1 = 0.f, a2 = 0.f, a3 = 0.f;
            float a4 = 0.f, a5 = 0.f, a6 = 0.f, a7 = 0.f;
            #pragma unroll 4
            for (int p = 0; p < NP; p++) {
                int o = h * NP + p;
                float w = g_PwT[o * NW + row];
                a0 = fmaf(sP[o], w, a0);
                a1 = fmaf(sP[FP + o], w, a1);
                a2 = fmaf(sP[2 * FP + o], w, a2);
                a3 = fmaf(sP[3 * FP + o], w, a3);
                a4 = fmaf(sP[4 * FP + o], w, a4);
                a5 = fmaf(sP[5 * FP + o], w, a5);
                a6 = fmaf(sP[6 * FP + o], w, a6);
                a7 = fmaf(sP[7 * FP + o], w, a7);
            }
            float b0 = 0.f, b1 = 0.f, b2 = 0.f, b3 = 0.f;
            float b4 = 0.f, b5 = 0.f, b6 = 0.f, b7 = 0.f;
            #pragma unroll 4
            for (int i = 0; i < NR * NM; i++) {
                int o = h * (NR * NM) + i;
                float w = g_RwT[o * NW + row];
                b0 = fmaf(sR[o], w, b0);
                b1 = fmaf(sR[FR + o], w, b1);
                b2 = fmaf(sR[2 * FR + o], w, b2);
                b3 = fmaf(sR[3 * FR + o], w, b3);
                b4 = fmaf(sR[4 * FR + o], w, b4);
                b5 = fmaf(sR[5 * FR + o], w, b5);
                b6 = fmaf(sR[6 * FR + o], w, b6);
                b7 = fmaf(sR[7 * FR + o], w, b7);
            }
            z0 = fmaf(a0, b0, z0);
            z1 = fmaf(a1, b1, z1);
            z2 = fmaf(a2, b2, z2);
            z3 = fmaf(a3, b3, z3);
            z4 = fmaf(a4, b4, z4);
            z5 = fmaf(a5, b5, z5);
            z6 = fmaf(a6, b6, z6);
            z7 = fmaf(a7, b7, z7);
        }
    }

    #pragma unroll
    for (int off = 16; off; off >>= 1) {
        z0 += __shfl_xor_sync(0xffffffffu, z0, off);
        z1 += __shfl_xor_sync(0xffffffffu, z1, off);
        z2 += __shfl_xor_sync(0xffffffffu, z2, off);
        z3 += __shfl_xor_sync(0xffffffffu, z3, off);
        z4 += __shfl_xor_sync(0xffffffffu, z4, off);
        z5 += __shfl_xor_sync(0xffffffffu, z5, off);
        z6 += __shfl_xor_sync(0xffffffffu, z6, off);
        z7 += __shfl_xor_sync(0xffffffffu, z7, off);
    }
    if ((t & 31) == 0) {
        atomicAdd(&zacc[0], z0);
        atomicAdd(&zacc[1], z1);
        atomicAdd(&zacc[2], z2);
        atomicAdd(&zacc[3], z3);
        atomicAdd(&zacc[4], z4);
        atomicAdd(&zacc[5], z5);
        atomicAdd(&zacc[6], z6);
        atomicAdd(&zacc[7], z7);
    }
    __syncthreads();

    // logsumexp(log x) == log(sum x); scores >= 0 so safe_log floor never binds
    if (t < TQ) g_Z[qbase + t] = zacc[t] + 2056.f * 1e-8f;
}

// ---------------- final loss reduction ----------------
__global__ void __launch_bounds__(1024) loss_kernel(const float* __restrict__ label_mask,
                                                    float* __restrict__ out)
{
    int t = threadIdx.x;  // t == b
    float num = 0.f, den = 0.f;
    float lz = logf(g_Z[t]);
    #pragma unroll 1
    for (int k = 0; k < NK; k++) {
        float lm = label_mask[t * NK + k];
        float p  = g_pos[t * NK + k] + 1e-8f;
        num += lm * (logf(fmaxf(p, 1e-8f)) - lz);
        den += lm;
    }
    __shared__ float sn[32], sd[32];
    #pragma unroll
    for (int off = 16; off; off >>= 1) {
        num += __shfl_xor_sync(0xffffffffu, num, off);
        den += __shfl_xor_sync(0xffffffffu, den, off);
    }
    if ((t & 31) == 0) { sn[t >> 5] = num; sd[t >> 5] = den; }
    __syncthreads();
    if (t < 32) {
        num = sn[t]; den = sd[t];
        #pragma unroll
        for (int off = 16; off; off >>= 1) {
            num += __shfl_xor_sync(0xffffffffu, num, off);
            den += __shfl_xor_sync(0xffffffffu, den, off);
        }
        if (t == 0) out[0] = -num / (den + 1e-6f);
    }
}

// ---------------- launch ----------------
extern "C" void kernel_launch(void* const* d_in, const int* in_sizes, int n_in,
                              void* d_out, int out_size)
{
    const int*   indices    = (const int*)  d_in[0];
    const float* mask       = (const float*)d_in[1];
    const int*   labels     = (const int*)  d_in[2];
    const float* label_mask = (const float*)d_in[3];
    const int*   neg_idx    = (const int*)  d_in[4];
    const float* etab       = (const float*)d_in[5];
    const float* kern       = (const float*)d_in[6];
    const float* omega      = (const float*)d_in[7];
    const float* anchors    = (const float*)d_in[8];
    float* out = (float*)d_out;

    // Gauss-Laguerre(2): nodes (2∓sqrt2)/C, weights (2±sqrt2)/4 (larger weight
    // pairs with smaller node), then /C; fold weight+1/sqrt(M) into c0/c1.
    const double Cc = 2.0 + 1e-6;
    const double r2 = 1.4142135623730951;
    float s0 = (float)((2.0 - r2) / Cc);
    float s1 = (float)((2.0 + r2) / Cc);
    float t0 = sqrtf(2.0f * s0);
    float t1 = sqrtf(2.0f * s1);
    float w0 = (float)(((2.0 + r2) / 4.0) / Cc);
    float w1 = (float)(((2.0 - r2) / 4.0) / Cc);
    float invM = 1.0f / sqrtf(32.0f + 1e-6f);
    float c0 = sqrtf(fmaxf(w0, 1e-6f)) * invM;
    float c1 = sqrtf(fmaxf(w1, 1e-6f)) * invM;

    anch_kernel<<<1, 256>>>(anchors);
    query_feat_kernel<<<NB, 256>>>(indices, mask, etab, omega, s0, s1, t0, t1, c0, c1);
    w_feat_kernel<<<NW, 256>>>(labels, neg_idx, kern, omega, s0, s1, t0, t1, c0, c1);
    score_kernel<<<NB / TQ, 512>>>();
    loss_kernel<<<1, NB>>>(label_mask, out);
}